// round 6
// baseline (speedup 1.0000x reference)
#include <cuda_runtime.h>
#include <math.h>

#define BS 32
#define NSAMP 64000
#define NTOT (BS*NSAMP)
#define TPB 128
#define BLK 16                 // XLA ReduceWindowRewriter base_length
#define NB1 (NSAMP/BLK)        // 4000 level-1 blocks per row
#define NB2 (NB1/BLK)          // 250 level-2 blocks
#define NB2P 256               // padded to multiple of 16
#define NB3 (NB2P/BLK)         // 16

__device__ float g_d[NTOT];      // increments fl(fl(2pi*f0) * fl(1/44100))
__device__ float g_off1[BS*NB1]; // exclusive offset for each level-1 block
__device__ float g_S1[BS*NB1];   // level-1 block sums

__device__ __forceinline__ float ex2f(float x){ float r; asm("ex2.approx.f32 %0, %1;":"=f"(r):"f"(x)); return r; }
__device__ __forceinline__ float lg2f(float x){ float r; asm("lg2.approx.f32 %0, %1;":"=f"(r):"f"(x)); return r; }

// 2*sigmoid(x)^ln(10) + 1e-7 ; rel err ~1e-6, amplitude-linear -> harmless
__device__ __forceinline__ float hfun(float x){
    float e = ex2f(-1.4426950408889634f * x);
    float u = lg2f(1.0f + e);
    return fmaf(2.0f, ex2f(-2.3025850929940457f * u), 1e-7f);
}

// increment: fast-math (arcp) form — multiply by compile-time-rounded reciprocal
__device__ __forceinline__ float incr(float f){
    const float RINV = 1.0f / 44100.0f;          // folded rn at compile time
    return __fmul_rn(__fmul_rn(6.283185307179586f, f), RINV);
}

// ---------------------------------------------------------------------------
// Kernel A: per 16-block — increments d and level-1 block sums S1
// (ascending left-fold == naive reduce_window evaluation order).
// ---------------------------------------------------------------------------
__global__ void prep_kernel(const float* __restrict__ f0){
    int j = blockIdx.x * blockDim.x + threadIdx.x;
    if (j >= BS * NB1) return;
    const float4* fp = (const float4*)(f0 + (size_t)j * BLK);
    float dv[BLK];
    #pragma unroll
    for (int i = 0; i < BLK/4; i++){
        float4 v = fp[i];
        dv[4*i+0] = incr(v.x);
        dv[4*i+1] = incr(v.y);
        dv[4*i+2] = incr(v.z);
        dv[4*i+3] = incr(v.w);
    }
    float acc = dv[0];
    #pragma unroll
    for (int i = 1; i < BLK; i++) acc = __fadd_rn(acc, dv[i]);
    float4* dd = (float4*)(g_d + (size_t)j * BLK);
    #pragma unroll
    for (int i = 0; i < BLK/4; i++)
        dd[i] = make_float4(dv[4*i], dv[4*i+1], dv[4*i+2], dv[4*i+3]);
    g_S1[j] = acc;
}

// ---------------------------------------------------------------------------
// Kernel B: per row — recursive 16-ary blocked scan of S1, emitting the
// exclusive level-1 offsets off1[j] = O2[j-1] (0 for j=0).
// ---------------------------------------------------------------------------
__global__ void __launch_bounds__(256) offsets_kernel(){
    __shared__ float sS1[NB1];
    __shared__ float sI2[NB1];
    __shared__ float sI3[NB2P];
    __shared__ float sO4[NB3];
    const int row = blockIdx.x, tid = threadIdx.x, nt = blockDim.x;
    const float* S1 = g_S1 + row * NB1;
    for (int i = tid; i < NB1; i += nt) sS1[i] = S1[i];
    __syncthreads();

    // level-2 inner folds: I2 = ascending inclusive fold of S1 within 16-blocks
    if (tid < NB2){
        int b = tid * BLK;
        float acc = sS1[b]; sI2[b] = acc;
        #pragma unroll
        for (int i = 1; i < BLK; i++){ acc = __fadd_rn(acc, sS1[b+i]); sI2[b+i] = acc; }
    }
    __syncthreads();

    // level-3: S2 = I2 block-ends (250 values, pad w/ exact 0 to 256); inner folds
    if (tid < NB3){
        int b = tid * BLK;
        float acc = 0.0f;
        #pragma unroll
        for (int i = 0; i < BLK; i++){
            int m = b + i;
            float s2 = (m < NB2) ? sI2[m*BLK + (BLK-1)] : 0.0f;
            acc = (i == 0) ? s2 : __fadd_rn(acc, s2);
            sI3[m] = acc;
        }
    }
    __syncthreads();

    // level-4 base case: sequential inclusive scan of the 16 S3 block-ends
    if (tid == 0){
        float acc = 0.0f;
        #pragma unroll
        for (int p = 0; p < NB3; p++){
            float s3 = sI3[p*BLK + (BLK-1)];
            acc = (p == 0) ? s3 : __fadd_rn(acc, s3);
            sO4[p] = acc;
        }
    }
    __syncthreads();

    // off1[j] = O2[j-1], with O2[m] = fl(O3excl + I2[m]), O3[m] = fl(O4excl + I3[m])
    float* off1 = g_off1 + row * NB1;
    for (int j = tid; j < NB1; j += nt){
        float v;
        if (j == 0) v = 0.0f;
        else {
            int jm = j - 1, q = jm >> 4;
            float o3e;
            if (q == 0) o3e = 0.0f;
            else {
                int qm = q - 1, p = qm >> 4;
                float o4e = (p == 0) ? 0.0f : sO4[p-1];
                o3e = __fadd_rn(o4e, sI3[qm]);
            }
            v = __fadd_rn(o3e, sI2[jm]);
        }
        off1[j] = v;
    }
}

// ---------------------------------------------------------------------------
// Oscillator: one thread per sample.
//   omega = fl(off1 + fold16(d))
//   theta = fl(omega + phase)
//   sin(fl(theta*k)) via accurate sincos(theta) + rotation + FMA residue corr.
// ---------------------------------------------------------------------------
__global__ void __launch_bounds__(TPB) osc_kernel(
    const float* __restrict__ f0,
    const float* __restrict__ amps,
    const float* __restrict__ phase,
    float* __restrict__ out)
{
    __shared__ float sA[TPB * 65];
    __shared__ float sD[TPB];
    __shared__ float sOFF[TPB / BLK];
    const int tid    = threadIdx.x;
    const int nchunk = NSAMP / TPB;
    const int b      = blockIdx.x / nchunk;
    const int t0     = (blockIdx.x % nchunk) * TPB;
    const int sbase  = b * NSAMP + t0;

    {   // coalesced stage: 128 samples x 65 floats (contiguous, 16B-aligned)
        const float4* gsrc = (const float4*)(amps + (size_t)sbase * 65);
        float4* sdst = (float4*)sA;
        #pragma unroll 4
        for (int i = tid; i < TPB * 65 / 4; i += TPB) sdst[i] = gsrc[i];
    }
    sD[tid] = g_d[sbase + tid];
    if (tid < TPB / BLK) sOFF[tid] = g_off1[(sbase >> 4) + tid];   // t0 multiple of 16
    __syncthreads();

    const int idx   = sbase + tid;
    const float f0v = f0[idx];

    // bit-exact omega/theta (within-16 ascending fold + one offset add)
    const int g = tid >> 4, i15 = tid & 15;
    float inc = sD[g * BLK];
    for (int i = 1; i <= i15; ++i) inc = __fadd_rn(inc, sD[g * BLK + i]);
    const float omega = __fadd_rn(sOFF[g], inc);
    const float theta = __fadd_rn(omega, phase[b]);

    // accurate sincos(theta): mod-pi in double (theta exact in f64)
    const double thd = (double)theta;
    const double qd  = rint(thd * 0.31830988618379067154);
    const int    q   = (int)qd;
    const double rd  = fma(-3.14159265358979323846, qd, thd);
    const float  r   = (float)rd;
    const float  rl  = (float)(rd - (double)r);

    const float r2 = r * r;
    float p = -2.5052108385441718e-8f;
    p = fmaf(p, r2,  2.7557319223985893e-6f);
    p = fmaf(p, r2, -1.9841269841269841e-4f);
    p = fmaf(p, r2,  8.3333333333333333e-3f);
    p = fmaf(p, r2, -1.6666666666666667e-1f);
    const float sp = fmaf(r * r2, p, r);
    float qq = 2.0876756987868099e-9f;
    qq = fmaf(qq, r2, -2.7557319223985888e-7f);
    qq = fmaf(qq, r2,  2.4801587301587302e-5f);
    qq = fmaf(qq, r2, -1.3888888888888889e-3f);
    qq = fmaf(qq, r2,  4.1666666666666664e-2f);
    qq = fmaf(qq, r2, -0.5f);
    const float cp = fmaf(qq, r2, 1.0f);

    float s1 = fmaf(cp,  rl, sp);
    float c1 = fmaf(-sp, rl, cp);
    const float sg = (q & 1) ? -1.0f : 1.0f;
    s1 *= sg; c1 *= sg;

    const float* my = sA + tid * 65;
    const float ta = hfun(my[0]);

    float s = 0.0f, c = 1.0f;
    float sum = 0.0f, acc = 0.0f;

    #pragma unroll
    for (int k = 1; k <= 64; ++k){
        const float kf = (float)k;
        float h = hfun(my[k]);
        float m = (__fmul_rn(f0v, kf) < 22050.0f) ? h : 0.0f;
        sum += m;

        // rotate to (sin(k*theta), cos(k*theta))
        float sn = fmaf(c, s1, s * c1);
        float cn = fmaf(-s, s1, c * c1);
        s = sn; c = cn;

        // reference argument is a = fl(theta*k) = theta*k - d (d exact via FMA)
        // sin(k*theta - d) ~= s*(1 - d^2/2) - c*d
        float a  = __fmul_rn(theta, kf);
        float d  = __fmaf_rn(theta, kf, -a);
        float w  = fmaf(d * d, -0.5f, 1.0f);
        float sv = fmaf(s, w, -(c * d));

        acc = fmaf(m, sv, acc);
    }

    out[idx] = acc * (ta / (sum + 1e-5f));
}

extern "C" void kernel_launch(void* const* d_in, const int* in_sizes, int n_in,
                              void* d_out, int out_size)
{
    const float* f0    = (const float*)d_in[0];
    const float* amps  = (const float*)d_in[1];
    const float* phase = (const float*)d_in[2];
    float* out = (float*)d_out;

    prep_kernel<<<(BS*NB1 + 255)/256, 256>>>(f0);
    offsets_kernel<<<BS, 256>>>();
    osc_kernel<<<(BS * NSAMP) / TPB, TPB>>>(f0, amps, phase, out);
}

// round 7
// speedup vs baseline: 1.1661x; 1.1661x over previous
#include <cuda_runtime.h>
#include <math.h>

#define BS 32
#define NSAMP 64000
#define NTOT (BS*NSAMP)
#define TPB 128
#define BLK 16                 // XLA ReduceWindowRewriter base_length
#define NB1 (NSAMP/BLK)        // 4000 level-1 blocks per row
#define NB2 (NB1/BLK)          // 250 level-2 blocks
#define NB2P 256               // padded to multiple of 16
#define NB3 (NB2P/BLK)         // 16

__device__ float g_off1[BS*NB1]; // exclusive offset for each level-1 block
__device__ float g_S1[BS*NB1];   // level-1 block sums

typedef unsigned long long u64;

__device__ __forceinline__ float ex2f(float x){ float r; asm("ex2.approx.f32 %0, %1;":"=f"(r):"f"(x)); return r; }
__device__ __forceinline__ float lg2f(float x){ float r; asm("lg2.approx.f32 %0, %1;":"=f"(r):"f"(x)); return r; }

// ---- packed f32x2 helpers (Blackwell; ptxas never emits these from C++) ----
__device__ __forceinline__ u64 pack2(float lo, float hi){ u64 r; asm("mov.b64 %0, {%1,%2};":"=l"(r):"f"(lo),"f"(hi)); return r; }
__device__ __forceinline__ void unpack2(u64 v, float& lo, float& hi){ asm("mov.b64 {%0,%1}, %2;":"=f"(lo),"=f"(hi):"l"(v)); }
__device__ __forceinline__ u64 fma2(u64 a,u64 b,u64 c){ u64 r; asm("fma.rn.f32x2 %0,%1,%2,%3;":"=l"(r):"l"(a),"l"(b),"l"(c)); return r; }
__device__ __forceinline__ u64 mul2(u64 a,u64 b){ u64 r; asm("mul.rn.f32x2 %0,%1,%2;":"=l"(r):"l"(a),"l"(b)); return r; }
__device__ __forceinline__ u64 add2(u64 a,u64 b){ u64 r; asm("add.rn.f32x2 %0,%1,%2;":"=l"(r):"l"(a),"l"(b)); return r; }

// 2*sigmoid(x)^ln(10) + 1e-7 (scalar, for total_amplitude)
__device__ __forceinline__ float hfun(float x){
    float e = ex2f(-1.4426950408889634f * x);
    float u = lg2f(1.0f + e);
    return fmaf(2.0f, ex2f(-2.3025850929940457f * u), 1e-7f);
}

// increment: fast-math (arcp) form — multiply by compile-time-rounded reciprocal
__device__ __forceinline__ float incr(float f){
    const float RINV = 1.0f / 44100.0f;
    return __fmul_rn(__fmul_rn(6.283185307179586f, f), RINV);
}

// ---------------------------------------------------------------------------
// Kernel A: level-1 block sums S1 only (increments recomputed in osc).
// ---------------------------------------------------------------------------
__global__ void prep_kernel(const float* __restrict__ f0){
    int j = blockIdx.x * blockDim.x + threadIdx.x;
    if (j >= BS * NB1) return;
    const float4* fp = (const float4*)(f0 + (size_t)j * BLK);
    float acc;
    #pragma unroll
    for (int i = 0; i < BLK/4; i++){
        float4 v = fp[i];
        float d0 = incr(v.x), d1 = incr(v.y), d2 = incr(v.z), d3 = incr(v.w);
        if (i == 0) acc = d0; else acc = __fadd_rn(acc, d0);
        acc = __fadd_rn(acc, d1);
        acc = __fadd_rn(acc, d2);
        acc = __fadd_rn(acc, d3);
    }
    g_S1[j] = acc;
}

// ---------------------------------------------------------------------------
// Kernel B: per row — recursive 16-ary blocked scan of S1 -> level-1 offsets.
// ---------------------------------------------------------------------------
__global__ void __launch_bounds__(256) offsets_kernel(){
    __shared__ float sS1[NB1];
    __shared__ float sI2[NB1];
    __shared__ float sI3[NB2P];
    __shared__ float sO4[NB3];
    const int row = blockIdx.x, tid = threadIdx.x, nt = blockDim.x;
    const float* S1 = g_S1 + row * NB1;
    for (int i = tid; i < NB1; i += nt) sS1[i] = S1[i];
    __syncthreads();

    if (tid < NB2){
        int b = tid * BLK;
        float acc = sS1[b]; sI2[b] = acc;
        #pragma unroll
        for (int i = 1; i < BLK; i++){ acc = __fadd_rn(acc, sS1[b+i]); sI2[b+i] = acc; }
    }
    __syncthreads();

    if (tid < NB3){
        int b = tid * BLK;
        float acc = 0.0f;
        #pragma unroll
        for (int i = 0; i < BLK; i++){
            int m = b + i;
            float s2 = (m < NB2) ? sI2[m*BLK + (BLK-1)] : 0.0f;
            acc = (i == 0) ? s2 : __fadd_rn(acc, s2);
            sI3[m] = acc;
        }
    }
    __syncthreads();

    if (tid == 0){
        float acc = 0.0f;
        #pragma unroll
        for (int p = 0; p < NB3; p++){
            float s3 = sI3[p*BLK + (BLK-1)];
            acc = (p == 0) ? s3 : __fadd_rn(acc, s3);
            sO4[p] = acc;
        }
    }
    __syncthreads();

    float* off1 = g_off1 + row * NB1;
    for (int j = tid; j < NB1; j += nt){
        float v;
        if (j == 0) v = 0.0f;
        else {
            int jm = j - 1, q = jm >> 4;
            float o3e;
            if (q == 0) o3e = 0.0f;
            else {
                int qm = q - 1, p = qm >> 4;
                float o4e = (p == 0) ? 0.0f : sO4[p-1];
                o3e = __fadd_rn(o4e, sI3[qm]);
            }
            v = __fadd_rn(o3e, sI2[jm]);
        }
        off1[j] = v;
    }
}

// ---------------------------------------------------------------------------
// Oscillator: one thread per sample; odd/even harmonic chains packed in f32x2.
// ---------------------------------------------------------------------------
__global__ void __launch_bounds__(TPB) osc_kernel(
    const float* __restrict__ f0,
    const float* __restrict__ amps,
    const float* __restrict__ phase,
    float* __restrict__ out)
{
    __shared__ float sA[TPB * 65];
    __shared__ float sD[TPB];
    __shared__ float sOFF[TPB / BLK];
    const int tid    = threadIdx.x;
    const int nchunk = NSAMP / TPB;
    const int b      = blockIdx.x / nchunk;
    const int t0     = (blockIdx.x % nchunk) * TPB;
    const int sbase  = b * NSAMP + t0;

    {   // coalesced stage: 128 samples x 65 floats (contiguous, 16B-aligned)
        const float4* gsrc = (const float4*)(amps + (size_t)sbase * 65);
        float4* sdst = (float4*)sA;
        #pragma unroll 4
        for (int i = tid; i < TPB * 65 / 4; i += TPB) sdst[i] = gsrc[i];
    }
    const int idx   = sbase + tid;
    const float f0v = f0[idx];
    sD[tid] = incr(f0v);                     // identical values to old g_d
    if (tid < TPB / BLK) sOFF[tid] = g_off1[(sbase >> 4) + tid];
    __syncthreads();

    // bit-exact omega/theta (within-16 ascending fold + one offset add)
    const int g = tid >> 4, i15 = tid & 15;
    float inc = sD[g * BLK];
    for (int i = 1; i <= i15; ++i) inc = __fadd_rn(inc, sD[g * BLK + i]);
    const float omega = __fadd_rn(sOFF[g], inc);
    const float theta = __fadd_rn(omega, phase[b]);

    // accurate sincos(theta): mod-pi in double
    const double thd = (double)theta;
    const double qd  = rint(thd * 0.31830988618379067154);
    const int    q   = (int)qd;
    const double rd  = fma(-3.14159265358979323846, qd, thd);
    const float  r   = (float)rd;
    const float  rl  = (float)(rd - (double)r);

    const float r2 = r * r;
    float p = -2.5052108385441718e-8f;
    p = fmaf(p, r2,  2.7557319223985893e-6f);
    p = fmaf(p, r2, -1.9841269841269841e-4f);
    p = fmaf(p, r2,  8.3333333333333333e-3f);
    p = fmaf(p, r2, -1.6666666666666667e-1f);
    const float sp = fmaf(r * r2, p, r);
    float qq = 2.0876756987868099e-9f;
    qq = fmaf(qq, r2, -2.7557319223985888e-7f);
    qq = fmaf(qq, r2,  2.4801587301587302e-5f);
    qq = fmaf(qq, r2, -1.3888888888888889e-3f);
    qq = fmaf(qq, r2,  4.1666666666666664e-2f);
    qq = fmaf(qq, r2, -0.5f);
    const float cp = fmaf(qq, r2, 1.0f);

    float s1 = fmaf(cp,  rl, sp);
    float c1 = fmaf(-sp, rl, cp);
    const float sg = (q & 1) ? -1.0f : 1.0f;
    s1 *= sg; c1 *= sg;

    // double-angle step (error ~1e-7, amplified < 3e-6 over 31 steps)
    const float s2v = 2.0f * s1 * c1;
    const float c2v = fmaf(-2.0f * s1, s1, 1.0f);

    // anti-alias cutoff: largest k with fl(f0*k) < 22050 (fl monotone in k)
    int kc = (int)(22050.0f / f0v);
    if (kc > 64) kc = 64;
    while (kc > 0  && __fmul_rn(f0v, (float)kc)     >= 22050.0f) --kc;
    while (kc < 64 && __fmul_rn(f0v, (float)(kc+1)) <  22050.0f) ++kc;

    const float* my = sA + tid * 65;
    const float ta = hfun(my[0]);

    // packed state: lane0 = odd harmonics, lane1 = even harmonics
    u64 S   = pack2(s1,  s2v);
    u64 C   = pack2(c1,  c2v);
    const u64 S2  = pack2(s2v,  s2v);
    const u64 C2  = pack2(c2v,  c2v);
    const u64 NS2 = pack2(-s2v, -s2v);
    const u64 TH  = pack2(theta,  theta);
    const u64 NTH = pack2(-theta, -theta);
    const u64 TWO = pack2(2.0f, 2.0f);
    const u64 L2E = pack2(-1.4426950408889634f, -1.4426950408889634f);
    const u64 ONE = pack2(1.0f, 1.0f);
    const u64 NLT = pack2(-2.3025850929940457f, -2.3025850929940457f);
    const u64 TWC = pack2(2.0f, 2.0f);
    const u64 EPS7= pack2(1e-7f, 1e-7f);
    u64 KF  = pack2(1.0f, 2.0f);
    u64 acc2 = pack2(0.0f, 0.0f);
    u64 sum2 = pack2(0.0f, 0.0f);

    #pragma unroll 8
    for (int j = 0; j < 32; ++j){
        const int kA = 2*j + 1;
        // amplitude transform (fma parts packed, MUFU scalar)
        u64 x2 = pack2(my[kA], my[kA+1]);
        u64 t2 = mul2(x2, L2E);
        float tA, tB; unpack2(t2, tA, tB);
        u64 e2 = pack2(ex2f(tA), ex2f(tB));
        u64 u2 = add2(e2, ONE);
        float uA, uB; unpack2(u2, uA, uB);
        u64 l2 = pack2(lg2f(uA), lg2f(uB));
        u64 v2 = mul2(l2, NLT);
        float vA, vB; unpack2(v2, vA, vB);
        u64 g2 = pack2(ex2f(vA), ex2f(vB));
        u64 h2 = fma2(g2, TWC, EPS7);
        float hA, hB; unpack2(h2, hA, hB);

        float mA = (kA     <= kc) ? hA : 0.0f;
        float mB = (kA + 1 <= kc) ? hB : 0.0f;
        u64 m2 = pack2(mA, mB);
        sum2 = add2(sum2, m2);

        // ref argument a = fl(theta*k); e = a - theta*k (exact via FMA)
        // sin(a) ~= sin(k*theta) + cos(k*theta)*e
        u64 a2  = mul2(TH, KF);
        u64 er2 = fma2(NTH, KF, a2);
        u64 sv2 = fma2(C, er2, S);
        acc2 = fma2(m2, sv2, acc2);

        // rotate both chains by 2*theta; advance k
        u64 Sn = fma2(C, S2, mul2(S, C2));
        u64 Cn = fma2(S, NS2, mul2(C, C2));
        S = Sn; C = Cn;
        KF = add2(KF, TWO);
    }

    float aA, aB, smA, smB;
    unpack2(acc2, aA, aB);
    unpack2(sum2, smA, smB);
    const float accT = aA + aB;
    const float sumT = smA + smB;
    out[idx] = accT * (ta / (sumT + 1e-5f));
}

extern "C" void kernel_launch(void* const* d_in, const int* in_sizes, int n_in,
                              void* d_out, int out_size)
{
    const float* f0    = (const float*)d_in[0];
    const float* amps  = (const float*)d_in[1];
    const float* phase = (const float*)d_in[2];
    float* out = (float*)d_out;

    prep_kernel<<<(BS*NB1 + 255)/256, 256>>>(f0);
    offsets_kernel<<<BS, 256>>>();
    osc_kernel<<<(BS * NSAMP) / TPB, TPB>>>(f0, amps, phase, out);
}

// round 8
// speedup vs baseline: 1.1859x; 1.0170x over previous
#include <cuda_runtime.h>
#include <math.h>

#define BS 32
#define NSAMP 64000
#define NTOT (BS*NSAMP)
#define TPB 128
#define BLK 16                 // XLA ReduceWindowRewriter base_length
#define NB1 (NSAMP/BLK)        // 4000 level-1 blocks per row
#define NB2 (NB1/BLK)          // 250 level-2 blocks
#define NB2P 256               // padded to multiple of 16
#define NB3 (NB2P/BLK)         // 16

__device__ float g_off1[BS*NB1]; // exclusive offset for each level-1 block

typedef unsigned long long u64;

__device__ __forceinline__ float ex2f(float x){ float r; asm("ex2.approx.f32 %0, %1;":"=f"(r):"f"(x)); return r; }
__device__ __forceinline__ float lg2f(float x){ float r; asm("lg2.approx.f32 %0, %1;":"=f"(r):"f"(x)); return r; }

// ---- packed f32x2 helpers ----
__device__ __forceinline__ u64 pack2(float lo, float hi){ u64 r; asm("mov.b64 %0, {%1,%2};":"=l"(r):"f"(lo),"f"(hi)); return r; }
__device__ __forceinline__ void unpack2(u64 v, float& lo, float& hi){ asm("mov.b64 {%0,%1}, %2;":"=f"(lo),"=f"(hi):"l"(v)); }
__device__ __forceinline__ u64 fma2(u64 a,u64 b,u64 c){ u64 r; asm("fma.rn.f32x2 %0,%1,%2,%3;":"=l"(r):"l"(a),"l"(b),"l"(c)); return r; }
__device__ __forceinline__ u64 mul2(u64 a,u64 b){ u64 r; asm("mul.rn.f32x2 %0,%1,%2;":"=l"(r):"l"(a),"l"(b)); return r; }
__device__ __forceinline__ u64 add2(u64 a,u64 b){ u64 r; asm("add.rn.f32x2 %0,%1,%2;":"=l"(r):"l"(a),"l"(b)); return r; }

// 2*sigmoid(x)^ln(10) + 1e-7 — scalar; constant muls become imm-form (rt 1)
__device__ __forceinline__ float hfun(float x){
    float e = ex2f(-1.4426950408889634f * x);
    float u = lg2f(1.0f + e);
    return fmaf(2.0f, ex2f(-2.3025850929940457f * u), 1e-7f);
}

// increment: fast-math (arcp) form — multiply by compile-time-rounded reciprocal
__device__ __forceinline__ float incr(float f){
    const float RINV = 1.0f / 44100.0f;
    return __fmul_rn(__fmul_rn(6.283185307179586f, f), RINV);
}

// ---------------------------------------------------------------------------
// Fused scan kernel: one block per row. S1 -> (in-place) I2 -> I3 -> O4 -> off1
// ---------------------------------------------------------------------------
__global__ void __launch_bounds__(512) scan_kernel(const float* __restrict__ f0){
    __shared__ float sI2[NB1];    // holds S1, then overwritten in place by I2
    __shared__ float sI3[NB2P];
    __shared__ float sO4[NB3];
    const int row = blockIdx.x, tid = threadIdx.x;
    const float* fr = f0 + (size_t)row * NSAMP;

    // level-1 block sums (ascending fold of increments within each 16-block)
    for (int j = tid; j < NB1; j += 512){
        const float4* fp = (const float4*)(fr + (size_t)j * BLK);
        float acc = 0.0f;
        #pragma unroll
        for (int i = 0; i < BLK/4; i++){
            float4 v = fp[i];
            float d0 = incr(v.x), d1 = incr(v.y), d2 = incr(v.z), d3 = incr(v.w);
            acc = (i == 0) ? d0 : __fadd_rn(acc, d0);
            acc = __fadd_rn(acc, d1);
            acc = __fadd_rn(acc, d2);
            acc = __fadd_rn(acc, d3);
        }
        sI2[j] = acc;
    }
    __syncthreads();

    // I2: ascending inclusive fold of S1 within 16-blocks (in place)
    if (tid < NB2){
        int b = tid * BLK;
        float acc = sI2[b];
        #pragma unroll
        for (int i = 1; i < BLK; i++){ acc = __fadd_rn(acc, sI2[b+i]); sI2[b+i] = acc; }
    }
    __syncthreads();

    // I3 from I2 block-ends (250 padded to 256 with exact 0)
    if (tid < NB3){
        int b = tid * BLK;
        float acc = 0.0f;
        #pragma unroll
        for (int i = 0; i < BLK; i++){
            int m = b + i;
            float s2 = (m < NB2) ? sI2[m*BLK + (BLK-1)] : 0.0f;
            acc = (i == 0) ? s2 : __fadd_rn(acc, s2);
            sI3[m] = acc;
        }
    }
    __syncthreads();

    // O4 base case
    if (tid == 0){
        float acc = 0.0f;
        #pragma unroll
        for (int p = 0; p < NB3; p++){
            float s3 = sI3[p*BLK + (BLK-1)];
            acc = (p == 0) ? s3 : __fadd_rn(acc, s3);
            sO4[p] = acc;
        }
    }
    __syncthreads();

    // off1[j] = O2[j-1]; O2[m] = fl(O3excl + I2[m]); O3[m] = fl(O4excl + I3[m])
    float* off1 = g_off1 + row * NB1;
    for (int j = tid; j < NB1; j += 512){
        float v;
        if (j == 0) v = 0.0f;
        else {
            int jm = j - 1, q = jm >> 4;
            float o3e;
            if (q == 0) o3e = 0.0f;
            else {
                int qm = q - 1, p = qm >> 4;
                float o4e = (p == 0) ? 0.0f : sO4[p-1];
                o3e = __fadd_rn(o4e, sI3[qm]);
            }
            v = __fadd_rn(o3e, sI2[jm]);
        }
        off1[j] = v;
    }
}

// ---------------------------------------------------------------------------
// Oscillator: one thread per sample; hfun scalar-batched (16 at a time, max
// MUFU ILP, no packing movs), rotation/correction/accumulate in f32x2.
// ---------------------------------------------------------------------------
__global__ void __launch_bounds__(TPB) osc_kernel(
    const float* __restrict__ f0,
    const float* __restrict__ amps,
    const float* __restrict__ phase,
    float* __restrict__ out)
{
    __shared__ float sA[TPB * 65];
    __shared__ float sD[TPB];
    __shared__ float sOFF[TPB / BLK];
    const int tid    = threadIdx.x;
    const int nchunk = NSAMP / TPB;
    const int b      = blockIdx.x / nchunk;
    const int t0     = (blockIdx.x % nchunk) * TPB;
    const int sbase  = b * NSAMP + t0;

    {   // coalesced stage: 128 samples x 65 floats (contiguous, 16B-aligned)
        const float4* gsrc = (const float4*)(amps + (size_t)sbase * 65);
        float4* sdst = (float4*)sA;
        #pragma unroll 4
        for (int i = tid; i < TPB * 65 / 4; i += TPB) sdst[i] = gsrc[i];
    }
    const int idx   = sbase + tid;
    const float f0v = f0[idx];
    sD[tid] = incr(f0v);
    if (tid < TPB / BLK) sOFF[tid] = g_off1[(sbase >> 4) + tid];
    __syncthreads();

    // bit-exact omega/theta (within-16 ascending fold + one offset add)
    const int g = tid >> 4, i15 = tid & 15;
    float inc = sD[g * BLK];
    for (int i = 1; i <= i15; ++i) inc = __fadd_rn(inc, sD[g * BLK + i]);
    const float omega = __fadd_rn(sOFF[g], inc);
    const float theta = __fadd_rn(omega, phase[b]);

    // accurate sincos(theta): mod-pi in double
    const double thd = (double)theta;
    const double qd  = rint(thd * 0.31830988618379067154);
    const int    q   = (int)qd;
    const double rd  = fma(-3.14159265358979323846, qd, thd);
    const float  r   = (float)rd;
    const float  rl  = (float)(rd - (double)r);

    const float r2 = r * r;
    float p = -2.5052108385441718e-8f;
    p = fmaf(p, r2,  2.7557319223985893e-6f);
    p = fmaf(p, r2, -1.9841269841269841e-4f);
    p = fmaf(p, r2,  8.3333333333333333e-3f);
    p = fmaf(p, r2, -1.6666666666666667e-1f);
    const float sp = fmaf(r * r2, p, r);
    float qq = 2.0876756987868099e-9f;
    qq = fmaf(qq, r2, -2.7557319223985888e-7f);
    qq = fmaf(qq, r2,  2.4801587301587302e-5f);
    qq = fmaf(qq, r2, -1.3888888888888889e-3f);
    qq = fmaf(qq, r2,  4.1666666666666664e-2f);
    qq = fmaf(qq, r2, -0.5f);
    const float cp = fmaf(qq, r2, 1.0f);

    float s1 = fmaf(cp,  rl, sp);
    float c1 = fmaf(-sp, rl, cp);
    const float sg = (q & 1) ? -1.0f : 1.0f;
    s1 *= sg; c1 *= sg;

    // double-angle step
    const float s2v = 2.0f * s1 * c1;
    const float c2v = fmaf(-2.0f * s1, s1, 1.0f);

    // anti-alias cutoff: largest k with fl(f0*k) < 22050 (monotone in k)
    int kc = (int)(22050.0f / f0v);
    if (kc > 64) kc = 64;
    while (kc > 0  && __fmul_rn(f0v, (float)kc)     >= 22050.0f) --kc;
    while (kc < 64 && __fmul_rn(f0v, (float)(kc+1)) <  22050.0f) ++kc;

    const float* my = sA + tid * 65;
    const float ta = hfun(my[0]);

    // packed state: lane0 = odd harmonics, lane1 = even harmonics
    u64 S   = pack2(s1,  s2v);
    u64 C   = pack2(c1,  c2v);
    const u64 S2  = pack2(s2v,  s2v);
    const u64 C2  = pack2(c2v,  c2v);
    const u64 NS2 = pack2(-s2v, -s2v);
    const u64 TH  = pack2(theta,  theta);
    const u64 NTH = pack2(-theta, -theta);
    const u64 TWO = pack2(2.0f, 2.0f);
    u64 KF  = pack2(1.0f, 2.0f);
    u64 acc2 = pack2(0.0f, 0.0f);
    u64 sum2 = pack2(0.0f, 0.0f);

    #pragma unroll
    for (int gb = 0; gb < 4; ++gb){
        // batch 16 independent hfun chains -> deep MUFU ILP, zero packing movs
        float h[16];
        #pragma unroll
        for (int i = 0; i < 16; ++i) h[i] = hfun(my[gb*16 + 1 + i]);

        const int kbase = gb * 16 + 1;
        #pragma unroll
        for (int jj = 0; jj < 8; ++jj){
            const int kA = kbase + 2*jj;
            float mA = (kA     <= kc) ? h[2*jj]   : 0.0f;
            float mB = (kA + 1 <= kc) ? h[2*jj+1] : 0.0f;
            u64 m2 = pack2(mA, mB);
            sum2 = add2(sum2, m2);

            // ref argument a = fl(theta*k); e = a - theta*k (exact via FMA)
            u64 a2  = mul2(TH, KF);
            u64 er2 = fma2(NTH, KF, a2);
            u64 sv2 = fma2(C, er2, S);      // sin(a) ~= s + c*e
            acc2 = fma2(m2, sv2, acc2);

            // rotate both chains by 2*theta; advance k
            u64 Sn = fma2(C, S2, mul2(S, C2));
            u64 Cn = fma2(S, NS2, mul2(C, C2));
            S = Sn; C = Cn;
            KF = add2(KF, TWO);
        }
    }

    float aA, aB, smA, smB;
    unpack2(acc2, aA, aB);
    unpack2(sum2, smA, smB);
    out[idx] = (aA + aB) * (ta / ((smA + smB) + 1e-5f));
}

extern "C" void kernel_launch(void* const* d_in, const int* in_sizes, int n_in,
                              void* d_out, int out_size)
{
    const float* f0    = (const float*)d_in[0];
    const float* amps  = (const float*)d_in[1];
    const float* phase = (const float*)d_in[2];
    float* out = (float*)d_out;

    scan_kernel<<<BS, 512>>>(f0);
    osc_kernel<<<(BS * NSAMP) / TPB, TPB>>>(f0, amps, phase, out);
}